// round 4
// baseline (speedup 1.0000x reference)
#include <cuda_runtime.h>
#include <math.h>

#define BT    16384
#define DOBS  512
#define DD    128
#define NS    16
#define HH    256
#define EPC   4      // entries per CTA in slot kernel

typedef unsigned long long u64;

__device__ __forceinline__ u64 fma2(u64 a, u64 b, u64 c) {
    u64 d;
    asm("fma.rn.f32x2 %0, %1, %2, %3;" : "=l"(d) : "l"(a), "l"(b), "l"(c));
    return d;
}
__device__ __forceinline__ float sum2(u64 a) {
    float2 f = *(float2*)&a;
    return f.x + f.y;
}
__device__ __forceinline__ u64 pack2(float lo, float hi) {
    u64 r;
    asm("mov.b64 %0, {%1, %2};" : "=l"(r) : "f"(lo), "f"(hi));
    return r;
}
__device__ __forceinline__ float tanha(float x) {
    float y;
    asm("tanh.approx.f32 %0, %1;" : "=f"(y) : "f"(x));
    return y;
}
__device__ __forceinline__ float sigm(float x) { return 0.5f * tanha(0.5f * x) + 0.5f; }

// ---------------- device scratch ----------------
__device__ float g_z[BT * DD];

// pair-interleaved packed weights
__device__ ulonglong2 pW1[128 * 256];
__device__ ulonglong2 pW2[64 * 128];
__device__ ulonglong2 pSkip[128 * 128];
__device__ ulonglong2 pWk[32 * 128];
__device__ ulonglong2 pWv[32 * 128];
__device__ ulonglong2 pWqT[32 * 128];
__device__ ulonglong2 pWih[32 * 384];
__device__ ulonglong2 pWhh[32 * 384];
__device__ ulonglong2 pmW1[32 * 128];
__device__ ulonglong2 pmW2[32 * 128];
__device__ ulonglong2 pWt[32 * 128];

// ---------------- fused pack kernel ----------------
__device__ __forceinline__ void pack_elem(const float* __restrict__ src,
                                          ulonglong2* __restrict__ dst, int C, int idx)
{
    int c = idx % C, k4 = idx / C;
    const float* s = src + (4 * k4) * C + c;
    ulonglong2 v;
    v.x = pack2(s[0], s[C]);
    v.y = pack2(s[2 * C], s[3 * C]);
    dst[idx] = v;
}
__device__ __forceinline__ void packT_elem(const float* __restrict__ src,
                                           ulonglong2* __restrict__ dst, int K, int C4, int idx)
{
    int i = idx % K, j4 = idx / K;
    const float* s = src + i * (C4 * 4) + 4 * j4;
    ulonglong2 v;
    v.x = pack2(s[0], s[1]);
    v.y = pack2(s[2], s[3]);
    dst[idx] = v;
}

__global__ __launch_bounds__(256) void pack_all(
    const float* __restrict__ eW1, const float* __restrict__ eW2,
    const float* __restrict__ skipW,
    const float* __restrict__ Wk, const float* __restrict__ Wv,
    const float* __restrict__ Wq,
    const float* __restrict__ gWih, const float* __restrict__ gWhh,
    const float* __restrict__ mW1, const float* __restrict__ mW2,
    const float* __restrict__ Wt)
{
    int idx = blockIdx.x * 256 + threadIdx.x;
    if (idx < 32768) { pack_elem(eW1,  pW1,  256, idx); return; }  idx -= 32768;
    if (idx < 8192)  { pack_elem(eW2,  pW2,  128, idx); return; }  idx -= 8192;
    if (idx < 16384) { pack_elem(skipW,pSkip,128, idx); return; }  idx -= 16384;
    if (idx < 4096)  { pack_elem(Wk,   pWk,  128, idx); return; }  idx -= 4096;
    if (idx < 4096)  { pack_elem(Wv,   pWv,  128, idx); return; }  idx -= 4096;
    if (idx < 4096)  { packT_elem(Wq,  pWqT, 128, 32, idx); return; } idx -= 4096;
    if (idx < 12288) { pack_elem(gWih, pWih, 384, idx); return; }  idx -= 12288;
    if (idx < 12288) { pack_elem(gWhh, pWhh, 384, idx); return; }  idx -= 12288;
    if (idx < 4096)  { pack_elem(mW1,  pmW1, 128, idx); return; }  idx -= 4096;
    if (idx < 4096)  { pack_elem(mW2,  pmW2, 128, idx); return; }  idx -= 4096;
    if (idx < 4096)  { pack_elem(Wt,   pWt,  128, idx); return; }
}

// ---------------------------------------------------------------------------
// Kernel 1: encoder (unchanged from R3)
// ---------------------------------------------------------------------------
__global__ __launch_bounds__(256) void enc_kernel(
    const float* __restrict__ obs,
    const float* __restrict__ b1, const float* __restrict__ b2)
{
    __shared__ __align__(16) float s_obs[8 * DOBS];
    __shared__ __align__(16) float s_h[8 * HH];
    __shared__ __align__(16) float s_p1[8 * DD];

    const int tid = threadIdx.x;
    const long e0 = (long)blockIdx.x * 8;
    const float* op = obs + e0 * DOBS;

    for (int i = tid; i < 8 * DOBS / 4; i += 256)
        ((float4*)s_obs)[i] = ((const float4*)op)[i];
    __syncthreads();

    {
        const int j = tid;
        u64 acc[8] = {0, 0, 0, 0, 0, 0, 0, 0};
        for (int d4 = 0; d4 < 128; d4++) {
            const ulonglong2 w = pW1[d4 * HH + j];
            #pragma unroll
            for (int r = 0; r < 8; r++) {
                const ulonglong2 s = *(const ulonglong2*)&s_obs[r * DOBS + 4 * d4];
                acc[r] = fma2(s.x, w.x, acc[r]);
                acc[r] = fma2(s.y, w.y, acc[r]);
            }
        }
        const float bj = b1[j];
        #pragma unroll
        for (int r = 0; r < 8; r++) {
            const float a = sum2(acc[r]) + bj;
            s_h[r * HH + j] = 0.5f * a * (1.f + erff(a * 0.70710678118654752f));
        }
    }
    __syncthreads();

    const int j = tid & 127;
    const int half = tid >> 7;
    u64 acc[8] = {0, 0, 0, 0, 0, 0, 0, 0};

    if (half == 0) {
        for (int d4 = 0; d4 < 64; d4++) {
            const ulonglong2 w = pW2[d4 * DD + j];
            #pragma unroll
            for (int r = 0; r < 8; r++) {
                const ulonglong2 s = *(const ulonglong2*)&s_h[r * HH + 4 * d4];
                acc[r] = fma2(s.x, w.x, acc[r]);
                acc[r] = fma2(s.y, w.y, acc[r]);
            }
        }
        for (int d4 = 0; d4 < 32; d4++) {
            const ulonglong2 w = pSkip[d4 * DD + j];
            #pragma unroll
            for (int r = 0; r < 8; r++) {
                const ulonglong2 s = *(const ulonglong2*)&s_obs[r * DOBS + 4 * d4];
                acc[r] = fma2(s.x, w.x, acc[r]);
                acc[r] = fma2(s.y, w.y, acc[r]);
            }
        }
    } else {
        for (int d4 = 32; d4 < 128; d4++) {
            const ulonglong2 w = pSkip[d4 * DD + j];
            #pragma unroll
            for (int r = 0; r < 8; r++) {
                const ulonglong2 s = *(const ulonglong2*)&s_obs[r * DOBS + 4 * d4];
                acc[r] = fma2(s.x, w.x, acc[r]);
                acc[r] = fma2(s.y, w.y, acc[r]);
            }
        }
        #pragma unroll
        for (int r = 0; r < 8; r++) s_p1[r * DD + j] = sum2(acc[r]);
    }
    __syncthreads();

    if (half == 0) {
        const float bj = b2[j];
        #pragma unroll
        for (int r = 0; r < 8; r++)
            g_z[(e0 + r) * DD + j] = tanha(sum2(acc[r]) + s_p1[r * DD + j] + bj);
    }
}

// ---------------------------------------------------------------------------
// Kernel 2: fused slot attention, EPC=4 entries per CTA, 512 threads.
// thread (j = tid&127, g = tid>>7). For GEMM phases, g = slot-row group
// (rows 4g..4g+3), looped over entries. For prologue, g = entry index.
// warp w owns slot row w (per entry) for LN / logits / normalize.
// ---------------------------------------------------------------------------
struct __align__(16) SlotSmem {
    float slots[EPC][NS * DD];   // 32 KB
    float ln[EPC][NS * DD];      // 32 KB
    float h1[EPC][NS * DD];      // 32 KB
    float inp[EPC][DD];
    float k[EPC][DD];
    float v[EPC][DD];
    float wqk[EPC][DD];
    float vwih[EPC][384];
    float lnp[512];              // [lsl_g|lsl_b|lml_g|lml_b]
    float logits[EPC][NS];
    float attn[EPC][NS];
    float red[EPC][12];
};

__global__ __launch_bounds__(512, 1) void slot_kernel(
    const float* __restrict__ slot_mu,
    const float* __restrict__ bih, const float* __restrict__ bhh,
    const float* __restrict__ mb1, const float* __restrict__ mb2,
    const float* __restrict__ lin_g, const float* __restrict__ lin_b,
    const float* __restrict__ lsl_g, const float* __restrict__ lsl_b,
    const float* __restrict__ lml_g, const float* __restrict__ lml_b,
    float* __restrict__ out)
{
    extern __shared__ __align__(16) char smem_raw[];
    SlotSmem& sm = *(SlotSmem*)smem_raw;

    const int tid = threadIdx.x, lane = tid & 31, warp = tid >> 5;
    const int j = tid & 127, g = tid >> 7;
    const long e0 = (long)blockIdx.x * EPC;

    // ---- prologue: LN of z for entry g (warps 4g..4g+3) ----
    const float zv = g_z[(e0 + g) * DD + j];
    {
        float s1 = zv, s2 = zv * zv;
        #pragma unroll
        for (int off = 16; off > 0; off >>= 1) {
            s1 += __shfl_down_sync(0xffffffffu, s1, off);
            s2 += __shfl_down_sync(0xffffffffu, s2, off);
        }
        if (lane == 0) { sm.red[g][warp & 3] = s1; sm.red[g][4 + (warp & 3)] = s2; }
    }
    // slots init (independent of barriers below — slots not read until later)
    {
        const float4* mu4 = (const float4*)slot_mu;
        #pragma unroll
        for (int r = 0; r < 4; r++) {
            float4 val = mu4[(tid & 127) + 128 * r];
            ((float4*)sm.slots[g])[(tid & 127) + 128 * r] = val;
        }
    }
    if (tid < 512) {
        sm.lnp[tid] = (tid < 128) ? lsl_g[tid]
                    : (tid < 256) ? lsl_b[tid - 128]
                    : (tid < 384) ? lml_g[tid - 256]
                                  : lml_b[tid - 384];
    }
    __syncthreads();
    if (j == 0) {
        float s = sm.red[g][0] + sm.red[g][1] + sm.red[g][2] + sm.red[g][3];
        float q = sm.red[g][4] + sm.red[g][5] + sm.red[g][6] + sm.red[g][7];
        const float mu = s * (1.f / 128.f);
        const float var = q * (1.f / 128.f) - mu * mu;
        sm.red[g][8] = mu;
        sm.red[g][9] = rsqrtf(var + 1e-5f);
    }
    __syncthreads();
    sm.inp[g][j] = (zv - sm.red[g][8]) * sm.red[g][9] * lin_g[j] + lin_b[j];
    __syncthreads();

    // ---- k and v for entry g ----
    {
        u64 acc = 0;
        for (int d4 = 0; d4 < 32; d4++) {
            const ulonglong2 s = *(const ulonglong2*)&sm.inp[g][4 * d4];
            const ulonglong2 w = pWk[d4 * DD + j];
            acc = fma2(s.x, w.x, acc);
            acc = fma2(s.y, w.y, acc);
        }
        sm.k[g][j] = sum2(acc);
        acc = 0;
        for (int d4 = 0; d4 < 32; d4++) {
            const ulonglong2 s = *(const ulonglong2*)&sm.inp[g][4 * d4];
            const ulonglong2 w = pWv[d4 * DD + j];
            acc = fma2(s.x, w.x, acc);
            acc = fma2(s.y, w.y, acc);
        }
        sm.v[g][j] = sum2(acc);
    }
    __syncthreads();

    // ---- wqk[g] and vwih[g] ----
    {
        u64 acc = 0;
        for (int j4 = 0; j4 < 32; j4++) {
            const ulonglong2 s = *(const ulonglong2*)&sm.k[g][4 * j4];
            const ulonglong2 w = pWqT[j4 * DD + j];
            acc = fma2(s.x, w.x, acc);
            acc = fma2(s.y, w.y, acc);
        }
        sm.wqk[g][j] = sum2(acc);
        #pragma unroll
        for (int p = 0; p < 3; p++) {
            const int c = j + 128 * p;
            u64 a2 = 0;
            for (int d4 = 0; d4 < 32; d4++) {
                const ulonglong2 s = *(const ulonglong2*)&sm.v[g][4 * d4];
                const ulonglong2 w = pWih[d4 * 384 + c];
                a2 = fma2(s.x, w.x, a2);
                a2 = fma2(s.y, w.y, a2);
            }
            sm.vwih[g][c] = sum2(a2);
        }
    }
    __syncthreads();

    const float invscale = 0.088388347648318447f;  // 1/sqrt(128)
    const float vw_r = sm.vwih[0][j];  // placeholder to keep compiler quiet (unused)
    (void)vw_r;
    const float bi_r = bih[j], bi_z = bih[j + 128], bi_n = bih[j + 256];
    const float bh_r = bhh[j], bh_z = bhh[j + 128], bh_n = bhh[j + 256];
    const float mb1_j = mb1[j], mb2_j = mb2[j];

    for (int it = 0; it < 3; it++) {
        // (a+b) LN(slots) + logits — warp w owns row w, loops entries
        #pragma unroll
        for (int e = 0; e < EPC; e++) {
            const float* src = &sm.slots[e][warp * DD];
            float x0 = src[lane], x1 = src[lane + 32], x2 = src[lane + 64], x3 = src[lane + 96];
            float s = x0 + x1 + x2 + x3;
            float q = x0 * x0 + x1 * x1 + x2 * x2 + x3 * x3;
            #pragma unroll
            for (int off = 16; off > 0; off >>= 1) {
                s += __shfl_down_sync(0xffffffffu, s, off);
                q += __shfl_down_sync(0xffffffffu, q, off);
            }
            s = __shfl_sync(0xffffffffu, s, 0);
            q = __shfl_sync(0xffffffffu, q, 0);
            const float mu = s * (1.f / 128.f);
            const float rstd = rsqrtf(q * (1.f / 128.f) - mu * mu + 1e-5f);
            const float n0 = (x0 - mu) * rstd * sm.lnp[lane]      + sm.lnp[128 + lane];
            const float n1 = (x1 - mu) * rstd * sm.lnp[lane + 32] + sm.lnp[160 + lane];
            const float n2 = (x2 - mu) * rstd * sm.lnp[lane + 64] + sm.lnp[192 + lane];
            const float n3 = (x3 - mu) * rstd * sm.lnp[lane + 96] + sm.lnp[224 + lane];
            float p = n0 * sm.wqk[e][lane] + n1 * sm.wqk[e][lane + 32]
                    + n2 * sm.wqk[e][lane + 64] + n3 * sm.wqk[e][lane + 96];
            #pragma unroll
            for (int off = 16; off > 0; off >>= 1) p += __shfl_down_sync(0xffffffffu, p, off);
            if (lane == 0) sm.logits[e][warp] = p * invscale;
        }
        __syncthreads();
        // (c) softmax: warp e handles entry e (lanes 0..15)
        if (warp < EPC && lane < 16) {
            const float l = sm.logits[warp][lane];
            float m = l;
            #pragma unroll
            for (int off = 8; off > 0; off >>= 1)
                m = fmaxf(m, __shfl_xor_sync(0xffffu, m, off));
            const float ex = __expf(l - m);
            float ssum = ex;
            #pragma unroll
            for (int off = 8; off > 0; off >>= 1)
                ssum += __shfl_xor_sync(0xffffu, ssum, off);
            sm.attn[warp][lane] = ex / ssum;
        }
        __syncthreads();

        // (d) GRU for all entries; stage new slots in regs, one barrier, write
        float nv[EPC][4];
        #pragma unroll
        for (int e = 0; e < EPC; e++) {
            u64 ar[4] = {0, 0, 0, 0}, az[4] = {0, 0, 0, 0}, an[4] = {0, 0, 0, 0};
            for (int d4 = 0; d4 < 32; d4++) {
                const ulonglong2 wr = pWhh[d4 * 384 + j];
                const ulonglong2 wz = pWhh[d4 * 384 + j + 128];
                const ulonglong2 wn = pWhh[d4 * 384 + j + 256];
                #pragma unroll
                for (int r = 0; r < 4; r++) {
                    const ulonglong2 sv = *(const ulonglong2*)&sm.slots[e][(4 * g + r) * DD + 4 * d4];
                    ar[r] = fma2(sv.x, wr.x, ar[r]);
                    ar[r] = fma2(sv.y, wr.y, ar[r]);
                    az[r] = fma2(sv.x, wz.x, az[r]);
                    az[r] = fma2(sv.y, wz.y, az[r]);
                    an[r] = fma2(sv.x, wn.x, an[r]);
                    an[r] = fma2(sv.y, wn.y, an[r]);
                }
            }
            const float vwr = sm.vwih[e][j], vwz = sm.vwih[e][j + 128], vwn = sm.vwih[e][j + 256];
            #pragma unroll
            for (int r = 0; r < 4; r++) {
                const int n = 4 * g + r;
                const float a = sm.attn[e][n];
                const float hr = sum2(ar[r]) + bh_r;
                const float hz = sum2(az[r]) + bh_z;
                const float hn = sum2(an[r]) + bh_n;
                const float rr = sigm(a * vwr + bi_r + hr);
                const float zz = sigm(a * vwz + bi_z + hz);
                const float nn = tanha(a * vwn + bi_n + rr * hn);
                const float h = sm.slots[e][n * DD + j];
                nv[e][r] = (1.f - zz) * nn + zz * h;
            }
        }
        __syncthreads();
        #pragma unroll
        for (int e = 0; e < EPC; e++)
            #pragma unroll
            for (int r = 0; r < 4; r++)
                sm.slots[e][(4 * g + r) * DD + j] = nv[e][r];
        __syncthreads();

        // (f) mlp-LN — warp w, row w, per entry
        #pragma unroll
        for (int e = 0; e < EPC; e++) {
            const float* src = &sm.slots[e][warp * DD];
            float x0 = src[lane], x1 = src[lane + 32], x2 = src[lane + 64], x3 = src[lane + 96];
            float s = x0 + x1 + x2 + x3;
            float q = x0 * x0 + x1 * x1 + x2 * x2 + x3 * x3;
            #pragma unroll
            for (int off = 16; off > 0; off >>= 1) {
                s += __shfl_down_sync(0xffffffffu, s, off);
                q += __shfl_down_sync(0xffffffffu, q, off);
            }
            s = __shfl_sync(0xffffffffu, s, 0);
            q = __shfl_sync(0xffffffffu, q, 0);
            const float mu = s * (1.f / 128.f);
            const float rstd = rsqrtf(q * (1.f / 128.f) - mu * mu + 1e-5f);
            float* dst = &sm.ln[e][warp * DD];
            dst[lane]      = (x0 - mu) * rstd * sm.lnp[256 + lane]      + sm.lnp[384 + lane];
            dst[lane + 32] = (x1 - mu) * rstd * sm.lnp[288 + lane]      + sm.lnp[416 + lane];
            dst[lane + 64] = (x2 - mu) * rstd * sm.lnp[320 + lane]      + sm.lnp[448 + lane];
            dst[lane + 96] = (x3 - mu) * rstd * sm.lnp[352 + lane]      + sm.lnp[480 + lane];
        }
        __syncthreads();

        // (g) h1 = relu(ln@W1 + b1), per entry
        #pragma unroll
        for (int e = 0; e < EPC; e++) {
            u64 acc[4] = {0, 0, 0, 0};
            for (int d4 = 0; d4 < 32; d4++) {
                const ulonglong2 w = pmW1[d4 * DD + j];
                #pragma unroll
                for (int r = 0; r < 4; r++) {
                    const ulonglong2 sv = *(const ulonglong2*)&sm.ln[e][(4 * g + r) * DD + 4 * d4];
                    acc[r] = fma2(sv.x, w.x, acc[r]);
                    acc[r] = fma2(sv.y, w.y, acc[r]);
                }
            }
            #pragma unroll
            for (int r = 0; r < 4; r++)
                sm.h1[e][(4 * g + r) * DD + j] = fmaxf(sum2(acc[r]) + mb1_j, 0.f);
        }
        __syncthreads();
        // (h) slots += h1@W2 + b2, per entry
        #pragma unroll
        for (int e = 0; e < EPC; e++) {
            u64 acc[4] = {0, 0, 0, 0};
            for (int d4 = 0; d4 < 32; d4++) {
                const ulonglong2 w = pmW2[d4 * DD + j];
                #pragma unroll
                for (int r = 0; r < 4; r++) {
                    const ulonglong2 sv = *(const ulonglong2*)&sm.h1[e][(4 * g + r) * DD + 4 * d4];
                    acc[r] = fma2(sv.x, w.x, acc[r]);
                    acc[r] = fma2(sv.y, w.y, acc[r]);
                }
            }
            #pragma unroll
            for (int r = 0; r < 4; r++)
                sm.slots[e][(4 * g + r) * DD + j] += sum2(acc[r]) + mb2_j;
        }
        __syncthreads();
    }

    // final F.normalize — warp w row w, per entry
    #pragma unroll
    for (int e = 0; e < EPC; e++) {
        const float* src = &sm.slots[e][warp * DD];
        float x0 = src[lane], x1 = src[lane + 32], x2 = src[lane + 64], x3 = src[lane + 96];
        float q = x0 * x0 + x1 * x1 + x2 * x2 + x3 * x3;
        #pragma unroll
        for (int off = 16; off > 0; off >>= 1) q += __shfl_down_sync(0xffffffffu, q, off);
        q = __shfl_sync(0xffffffffu, q, 0);
        const float inv = 1.f / fmaxf(sqrtf(q), 1e-8f);
        float* dst = out + (e0 + e) * (NS * DD) + warp * DD;
        dst[lane]      = x0 * inv;
        dst[lane + 32] = x1 * inv;
        dst[lane + 64] = x2 * inv;
        dst[lane + 96] = x3 * inv;
    }
}

// ---------------------------------------------------------------------------
// Kernel 3: persistent temporal blend (unchanged)
// ---------------------------------------------------------------------------
__global__ __launch_bounds__(512) void temporal_kernel(float* __restrict__ out)
{
    __shared__ __align__(16) float s_prev[NS * DD];
    const int tid = threadIdx.x;
    const int j = tid & 127;
    const int g = tid >> 7;
    const long b = blockIdx.x;
    float* base = out + b * 64 * (NS * DD);

    for (int i = tid; i < NS * DD; i += 512) s_prev[i] = base[i];
    __syncthreads();

    for (int t = 1; t < 64; t++) {
        float* cur = base + t * (NS * DD);
        float c[4];
        #pragma unroll
        for (int r = 0; r < 4; r++) c[r] = cur[(g * 4 + r) * DD + j];

        u64 acc[4] = {0, 0, 0, 0};
        for (int d4 = 0; d4 < 32; d4++) {
            const ulonglong2 w = pWt[d4 * DD + j];
            #pragma unroll
            for (int r = 0; r < 4; r++) {
                const ulonglong2 s = *(const ulonglong2*)&s_prev[(g * 4 + r) * DD + 4 * d4];
                acc[r] = fma2(s.x, w.x, acc[r]);
                acc[r] = fma2(s.y, w.y, acc[r]);
            }
        }
        __syncthreads();
        #pragma unroll
        for (int r = 0; r < 4; r++) {
            const float v = 0.7f * c[r] + 0.3f * tanha(sum2(acc[r]));
            cur[(g * 4 + r) * DD + j] = v;
            s_prev[(g * 4 + r) * DD + j] = v;
        }
        __syncthreads();
    }
}

// ---------------------------------------------------------------------------
extern "C" void kernel_launch(void* const* d_in, const int* in_sizes, int n_in,
                              void* d_out, int out_size)
{
    const float* obs    = (const float*)d_in[0];
    const float* eW1    = (const float*)d_in[1];
    const float* eb1    = (const float*)d_in[2];
    const float* eW2    = (const float*)d_in[3];
    const float* eb2    = (const float*)d_in[4];
    const float* skipW  = (const float*)d_in[5];
    const float* smu    = (const float*)d_in[6];
    const float* Wk     = (const float*)d_in[7];
    const float* Wv     = (const float*)d_in[8];
    const float* Wq     = (const float*)d_in[9];
    const float* gWih   = (const float*)d_in[10];
    const float* gWhh   = (const float*)d_in[11];
    const float* gbih   = (const float*)d_in[12];
    const float* gbhh   = (const float*)d_in[13];
    const float* mW1    = (const float*)d_in[14];
    const float* mb1    = (const float*)d_in[15];
    const float* mW2    = (const float*)d_in[16];
    const float* mb2    = (const float*)d_in[17];
    const float* lin_g  = (const float*)d_in[18];
    const float* lin_b  = (const float*)d_in[19];
    const float* lsl_g  = (const float*)d_in[20];
    const float* lsl_b  = (const float*)d_in[21];
    const float* lml_g  = (const float*)d_in[22];
    const float* lml_b  = (const float*)d_in[23];
    const float* Wt     = (const float*)d_in[24];
    float* out = (float*)d_out;

    static int smem_set = 0;
    const int smem_bytes = (int)sizeof(SlotSmem);
    if (!smem_set) {
        cudaFuncSetAttribute(slot_kernel,
                             cudaFuncAttributeMaxDynamicSharedMemorySize, smem_bytes);
        smem_set = 1;
    }

    pack_all<<<(106496 + 255) / 256, 256>>>(eW1, eW2, skipW, Wk, Wv, Wq,
                                            gWih, gWhh, mW1, mW2, Wt);

    enc_kernel<<<BT / 8, 256>>>(obs, eb1, eb2);

    slot_kernel<<<BT / EPC, 512, smem_bytes>>>(smu, gbih, gbhh, mb1, mb2,
                                               lin_g, lin_b, lsl_g, lsl_b,
                                               lml_g, lml_b, out);

    temporal_kernel<<<256, 512>>>(out);
}